// round 17
// baseline (speedup 1.0000x reference)
#include <cuda_runtime.h>
#include <cuda_fp16.h>
#include <string.h>

// Problem constants
#define DD 160
#define HH 192
#define WW 160
#define HW (HH*WW)
#define DHW (DD*HH*WW)          // 4,915,200
#define BB 2

// z-pair, channel-interleaved HALF copy of x, 8 bytes per voxel:
// g_hpair[b*DHW + s] = { h2(ch0[z],ch1[z]), h2(ch0[z+1c],ch1[z+1c]) }  (z+1 clamped)
__device__ uint2 g_hpair[BB * DHW];   // 78.6 MB -> fits L2

__device__ __forceinline__ unsigned int h2_as_u(__half2 h) {
    unsigned int u; memcpy(&u, &h, 4); return u;
}
__device__ __forceinline__ __half2 u_as_h2(unsigned int u) {
    __half2 h; memcpy(&h, &u, 4); return h;
}

// ---------------------------------------------------------------------------
// Pre-pass: build half z-pair copy, 4 x-voxels per thread (float4 reads,
// 2x uint4 writes). Rows are 160 long (mult of 4) -> a quad never crosses a
// row or z boundary. z+1 plane re-read hits L2.
// ---------------------------------------------------------------------------
__global__ __launch_bounds__(256)
void hpair_kernel(const float* __restrict__ x)
{
    int j = blockIdx.x * blockDim.x + threadIdx.x;   // quad index
    const int NJ = DHW / 4;
    if (j >= BB * NJ) return;
    int b = j / NJ;
    int jj = j - b * NJ;
    int s = 4 * jj;
    int z = s / HW;
    int dzp = (z + 1 < DD) ? HW : 0;

    const float* c0 = x + (size_t)b * 2 * DHW;
    const float* c1 = c0 + DHW;

    float4 a0 = __ldg((const float4*)(c0 + s));        // ch0 @ z
    float4 a1 = __ldg((const float4*)(c1 + s));        // ch1 @ z
    float4 b0 = __ldg((const float4*)(c0 + s + dzp));  // ch0 @ z+1
    float4 b1 = __ldg((const float4*)(c1 + s + dzp));  // ch1 @ z+1

    uint4 o0, o1;
    o0.x = h2_as_u(__floats2half2_rn(a0.x, a1.x));
    o0.y = h2_as_u(__floats2half2_rn(b0.x, b1.x));
    o0.z = h2_as_u(__floats2half2_rn(a0.y, a1.y));
    o0.w = h2_as_u(__floats2half2_rn(b0.y, b1.y));
    o1.x = h2_as_u(__floats2half2_rn(a0.z, a1.z));
    o1.y = h2_as_u(__floats2half2_rn(b0.z, b1.z));
    o1.z = h2_as_u(__floats2half2_rn(a0.w, a1.w));
    o1.w = h2_as_u(__floats2half2_rn(b0.w, b1.w));

    uint4* dst = (uint4*)(g_hpair + (size_t)b * DHW + s);
    dst[0] = o0;
    dst[1] = o1;
}

// ---------------------------------------------------------------------------
// Main warp kernel: 4 consecutive x-voxels per thread.
// Per voxel: 4 x 8B gathers (both z-corners x both channels each).
// Flow: 3 float4 loads; output: 2 float4 stores.
// ---------------------------------------------------------------------------
__global__ __launch_bounds__(256)
void warp3d_kernel(const float* __restrict__ flow,
                   float* __restrict__ out)
{
    int j = blockIdx.x * blockDim.x + threadIdx.x;   // quad index
    const int NQ = DHW / 4;
    if (j >= BB * NQ) return;
    int b = j / NQ;
    int jq = j - b * NQ;
    int s = 4 * jq;                                  // first voxel of the quad

    int xw0 = s % WW;         // quad start x (4-aligned)
    int t   = s / WW;
    int yh  = t % HH;
    int zd  = t / HH;

    const float* fb = flow + (size_t)b * 3 * DHW;
    float4 fz4 = __ldg((const float4*)(fb + s));
    float4 fy4 = __ldg((const float4*)(fb + s + DHW));
    float4 fx4 = __ldg((const float4*)(fb + s + 2 * DHW));

    const uint2* qb = g_hpair + (size_t)b * DHW;

    float oz[4], oo[4];   // per-voxel results, ch0 / ch1
    float fzl[4] = {fz4.x, fz4.y, fz4.z, fz4.w};
    float fyl[4] = {fy4.x, fy4.y, fy4.z, fy4.w};
    float fxl[4] = {fx4.x, fx4.y, fx4.z, fx4.w};

#pragma unroll
    for (int v = 0; v < 4; v++) {
        float pz = (float)zd + fzl[v];
        float py = (float)yh + fyl[v];
        float px = (float)(xw0 + v) + fxl[v];

        float z0f = floorf(pz), y0f = floorf(py), x0f = floorf(px);
        float fz = pz - z0f, fy = py - y0f, fx = px - x0f;
        int z0 = (int)z0f, y0 = (int)y0f, x0 = (int)x0f;
        int z1 = z0 + 1, y1 = y0 + 1, x1 = x0 + 1;

        float wz0 = (z0 >= 0 && z0 < DD) ? (1.0f - fz) : 0.0f;
        float wz1 = (z1 >= 0 && z1 < DD) ? fz          : 0.0f;
        float wy0 = (y0 >= 0 && y0 < HH) ? (1.0f - fy) : 0.0f;
        float wy1 = (y1 >= 0 && y1 < HH) ? fy          : 0.0f;
        float wx0 = (x0 >= 0 && x0 < WW) ? (1.0f - fx) : 0.0f;
        float wx1 = (x1 >= 0 && x1 < WW) ? fx          : 0.0f;

        int yc0 = min(max(y0, 0), HH - 1);
        int yc1 = min(max(y1, 0), HH - 1);
        int xc0 = min(max(x0, 0), WW - 1);
        int xc1 = min(max(x1, 0), WW - 1);

        // z-pair gather: pi = clamp(z0); pair = (v[pi], v[min(pi+1,DD-1)])
        //  z0 >= 0 : lo=slot0, hi=slot1;  z0 == -1: wz0=0, v[0]=slot0 -> hi=slot0
        int pi = min(max(z0, 0), DD - 1);
        bool zlo = (z0 >= 0);

        int base0 = (pi * HH + yc0) * WW;
        int base1 = (pi * HH + yc1) * WW;

        float wy0x0 = wy0 * wx0, wy0x1 = wy0 * wx1;
        float wy1x0 = wy1 * wx0, wy1x1 = wy1 * wx1;

        uint2 q00 = __ldg(qb + base0 + xc0);
        uint2 q01 = __ldg(qb + base0 + xc1);
        uint2 q10 = __ldg(qb + base1 + xc0);
        uint2 q11 = __ldg(qb + base1 + xc1);

        float a0 = 0.0f, a1 = 0.0f;
        {
            float2 vlo = __half22float2(u_as_h2(q00.x));
            float2 vhi = __half22float2(u_as_h2(zlo ? q00.y : q00.x));
            a0 = fmaf(wy0x0, fmaf(wz0, vlo.x, wz1 * vhi.x), a0);
            a1 = fmaf(wy0x0, fmaf(wz0, vlo.y, wz1 * vhi.y), a1);
        }
        {
            float2 vlo = __half22float2(u_as_h2(q01.x));
            float2 vhi = __half22float2(u_as_h2(zlo ? q01.y : q01.x));
            a0 = fmaf(wy0x1, fmaf(wz0, vlo.x, wz1 * vhi.x), a0);
            a1 = fmaf(wy0x1, fmaf(wz0, vlo.y, wz1 * vhi.y), a1);
        }
        {
            float2 vlo = __half22float2(u_as_h2(q10.x));
            float2 vhi = __half22float2(u_as_h2(zlo ? q10.y : q10.x));
            a0 = fmaf(wy1x0, fmaf(wz0, vlo.x, wz1 * vhi.x), a0);
            a1 = fmaf(wy1x0, fmaf(wz0, vlo.y, wz1 * vhi.y), a1);
        }
        {
            float2 vlo = __half22float2(u_as_h2(q11.x));
            float2 vhi = __half22float2(u_as_h2(zlo ? q11.y : q11.x));
            a0 = fmaf(wy1x1, fmaf(wz0, vlo.x, wz1 * vhi.x), a0);
            a1 = fmaf(wy1x1, fmaf(wz0, vlo.y, wz1 * vhi.y), a1);
        }
        oz[v] = a0;
        oo[v] = a1;
    }

    float* ob = out + (size_t)b * 2 * DHW;
    *((float4*)(ob + s))       = make_float4(oz[0], oz[1], oz[2], oz[3]);
    *((float4*)(ob + s + DHW)) = make_float4(oo[0], oo[1], oo[2], oo[3]);
}

extern "C" void kernel_launch(void* const* d_in, const int* in_sizes, int n_in,
                              void* d_out, int out_size)
{
    const float* x    = (const float*)d_in[0];
    const float* flow = (const float*)d_in[1];
    float* out        = (float*)d_out;

    const int threads = 256;
    {
        const int NJ = BB * (DHW / 4);
        hpair_kernel<<<(NJ + threads - 1) / threads, threads>>>(x);
    }
    {
        const int NQ = BB * (DHW / 4);
        warp3d_kernel<<<(NQ + threads - 1) / threads, threads>>>(flow, out);
    }
}